// round 14
// baseline (speedup 1.0000x reference)
#include <cuda_runtime.h>
#include <cstdint>

#define N_NODES 8192
#define F_DIM   256
#define MN      ((size_t)N_NODES * F_DIM)

// Persistent-G2 work assignment: 2048 units = 128 tiles x 16 k-chunks(512).
// 296 CTAs: first 272 own 7 units, last 24 own 6. (272*7 + 24*6 = 2048)
#define NCTA_P   296
#define BIGQ     1904     // 272*7

// Scratch (no cudaMalloc allowed)
__device__ float g_hT[(size_t)F_DIM * N_NODES];   // rna(neigh_W @ feat^T) [256][8192]
__device__ float g_agg[MN];                        // (adj@h)/deg, tf32-rounded
__device__ float g_feat[MN];                       // tf32-rounded features
__device__ float g_part[4 * MN];                   // per-slot partials (32MB)
__device__ float g_rowp[4 * N_NODES];              // per-slot partial rowsums

// ---------------------------------------------------------------------------
// helpers
// ---------------------------------------------------------------------------
__device__ __forceinline__ void cp_async16(uint32_t s, const void* g) {
    asm volatile("cp.async.cg.shared.global [%0], [%1], 16;\n" :: "r"(s), "l"(g));
}
__device__ __forceinline__ void cp_commit() { asm volatile("cp.async.commit_group;\n"); }
template <int N> __device__ __forceinline__ void cp_wait() {
    asm volatile("cp.async.wait_group %0;\n" :: "n"(N));
}
__device__ __forceinline__ float rna_tf32(float f) {
    uint32_t r;
    asm("cvt.rna.tf32.f32 %0, %1;\n" : "=r"(r) : "f"(f));
    return __uint_as_float(r);
}
__device__ __forceinline__ void mma_tf32(float* c, const uint32_t* a, const uint32_t* b) {
    asm volatile(
        "mma.sync.aligned.m16n8k8.row.col.f32.tf32.tf32.f32 "
        "{%0,%1,%2,%3}, {%4,%5,%6,%7}, {%8,%9}, {%0,%1,%2,%3};\n"
        : "+f"(c[0]), "+f"(c[1]), "+f"(c[2]), "+f"(c[3])
        : "r"(a[0]), "r"(a[1]), "r"(a[2]), "r"(a[3]), "r"(b[0]), "r"(b[1]));
}
__device__ __forceinline__ void ldsm_x4(uint32_t& r0, uint32_t& r1, uint32_t& r2,
                                        uint32_t& r3, uint32_t a) {
    asm volatile("ldmatrix.sync.aligned.m8n8.x4.shared.b16 {%0,%1,%2,%3}, [%4];\n"
                 : "=r"(r0), "=r"(r1), "=r"(r2), "=r"(r3) : "r"(a));
}
__device__ __forceinline__ int unit_owner(int u) {
    return (u < BIGQ) ? (u / 7) : (272 + (u - BIGQ) / 6);
}

// ---------------------------------------------------------------------------
__global__ void round_copy_kernel(const float* __restrict__ src, float* __restrict__ dst) {
    const size_t i = (size_t)(blockIdx.x * blockDim.x + threadIdx.x) * 4;
    float4 v = *reinterpret_cast<const float4*>(src + i);
    v.x = rna_tf32(v.x); v.y = rna_tf32(v.y);
    v.z = rna_tf32(v.z); v.w = rna_tf32(v.w);
    *reinterpret_cast<float4*>(dst + i) = v;
}

// zero slot 3 of part + rowp (slots 0-2 always written by the persistent GEMM)
__global__ void zero_slot3_kernel(float* __restrict__ part, float* __restrict__ rowp) {
    const size_t g = (size_t)blockIdx.x * blockDim.x + threadIdx.x;
    *reinterpret_cast<float4*>(part + 3 * MN + g * 4) = make_float4(0, 0, 0, 0);
    if (g < N_NODES / 4)
        *reinterpret_cast<float4*>(rowp + 3 * N_NODES + g * 4) = make_float4(0, 0, 0, 0);
}

__global__ void reduce_big_kernel(const float* __restrict__ part,
                                  const float* __restrict__ rowp,
                                  float* __restrict__ agg) {
    const size_t i = (size_t)(blockIdx.x * blockDim.x + threadIdx.x) * 4;
    const int row = (int)(i >> 8);
    const float inv = 1.0f / (rowp[row] + rowp[N_NODES + row] +
                              rowp[2 * N_NODES + row] + rowp[3 * N_NODES + row] + 1.0f);
    float4 a = *reinterpret_cast<const float4*>(part + i);
    float4 b = *reinterpret_cast<const float4*>(part + MN + i);
    float4 c = *reinterpret_cast<const float4*>(part + 2 * MN + i);
    float4 d = *reinterpret_cast<const float4*>(part + 3 * MN + i);
    float4 o;
    o.x = rna_tf32((a.x + b.x + c.x + d.x) * inv);
    o.y = rna_tf32((a.y + b.y + c.y + d.y) * inv);
    o.z = rna_tf32((a.z + b.z + c.z + d.z) * inv);
    o.w = rna_tf32((a.w + b.w + c.w + d.w) * inv);
    *reinterpret_cast<float4*>(agg + i) = o;
}

// ---------------------------------------------------------------------------
// NARROW kernel: tile 128x128x32, 256 threads, 2 CTAs/SM (GEMM1 + concat GEMM3)
// ---------------------------------------------------------------------------
#define A_FLTS 4608              // 128*36
#define STAGE_FLTS_N (2 * A_FLTS)
#define NSTAGE 3
#define SMEM_N (NSTAGE * STAGE_FLTS_N * 4)   // 110592

template <bool CONCAT, bool ROUND_OUT>
__global__ __launch_bounds__(256, 2)
void tgemm(const float* __restrict__ A, const float* __restrict__ A2,
           const float* __restrict__ B, float* __restrict__ C,
           int K, int lda, int ldb, int ldc)
{
    extern __shared__ float sm[];
    const int tid  = threadIdx.x;
    const int lane = tid & 31;
    const int wid  = tid >> 5;
    const int wm   = wid & 1;
    const int wn   = wid >> 1;
    const int bm   = blockIdx.y * 128;
    const int bn   = blockIdx.x * 128;

    const uint32_t smem_base = (uint32_t)__cvta_generic_to_shared(sm);

    float acc[4][4][4];
    #pragma unroll
    for (int i = 0; i < 4; i++)
        #pragma unroll
        for (int j = 0; j < 4; j++)
            #pragma unroll
            for (int r = 0; r < 4; r++) acc[i][j][r] = 0.0f;

    uint32_t a_off, b_off;
    {
        const int ar = wm * 64 + (lane & 7) + ((lane >> 3) & 1) * 8;
        const int ak = ((lane >> 4) & 1) * 4;
        a_off = (uint32_t)(ar * 36 + ak) * 4u;
        const int br = wn * 32 + ((lane >> 4) & 1) * 8 + (lane & 7);
        const int bk = ((lane >> 3) & 1) * 4;
        b_off = (uint32_t)(br * 36 + bk) * 4u + A_FLTS * 4u;
    }

    const int a_r  = tid >> 3;
    const int a_kv = (tid & 7) * 4;

    auto fill = [&](int t) {
        const int k0 = t * 32;
        const int s  = t % NSTAGE;
        const uint32_t sA = smem_base + (uint32_t)(s * STAGE_FLTS_N) * 4u;
        const uint32_t sB = sA + A_FLTS * 4u;
        const float* Asrc = A;
        int ka = k0;
        if (CONCAT && k0 >= F_DIM) { Asrc = A2; ka = k0 - F_DIM; }
        #pragma unroll
        for (int p = 0; p < 4; p++) {
            const int r = a_r + 32 * p;
            cp_async16(sA + (uint32_t)(r * 36 + a_kv) * 4u,
                       Asrc + (size_t)(bm + r) * lda + ka + a_kv);
        }
        #pragma unroll
        for (int p = 0; p < 4; p++) {
            const int n = a_r + 32 * p;
            cp_async16(sB + (uint32_t)(n * 36 + a_kv) * 4u,
                       B + (size_t)(bn + n) * ldb + k0 + a_kv);
        }
    };

    const int T = K >> 5;
    fill(0); cp_commit();
    fill(1); cp_commit();

    for (int t = 0; t < T; t++) {
        cp_wait<1>();
        __syncthreads();
        if (t + 2 < T) fill(t + 2);
        cp_commit();

        const int s = t % NSTAGE;
        const uint32_t stage_b = smem_base + (uint32_t)(s * STAGE_FLTS_N) * 4u;
        const uint32_t a_base = stage_b + a_off;
        const uint32_t b_base = stage_b + b_off;

        #pragma unroll
        for (int k8 = 0; k8 < 32; k8 += 8) {
            const uint32_t kb = (uint32_t)k8 * 4u;
            uint32_t af[4][4];
            #pragma unroll
            for (int mi = 0; mi < 4; mi++)
                ldsm_x4(af[mi][0], af[mi][1], af[mi][2], af[mi][3],
                        a_base + kb + (uint32_t)(mi * 16 * 36) * 4u);
            uint32_t bf[4][2];
            #pragma unroll
            for (int pi = 0; pi < 2; pi++)
                ldsm_x4(bf[2 * pi][0], bf[2 * pi][1], bf[2 * pi + 1][0], bf[2 * pi + 1][1],
                        b_base + kb + (uint32_t)(pi * 16 * 36) * 4u);
            #pragma unroll
            for (int mi = 0; mi < 4; mi++)
                #pragma unroll
                for (int ni = 0; ni < 4; ni++)
                    mma_tf32(acc[mi][ni], af[mi], bf[ni]);
        }
    }

    #pragma unroll
    for (int mi = 0; mi < 4; mi++) {
        const int r0 = bm + wm * 64 + mi * 16 + (lane >> 2);
        #pragma unroll
        for (int ni = 0; ni < 4; ni++) {
            const int c0 = bn + wn * 32 + ni * 8 + 2 * (lane & 3);
            float* p0 = C + (size_t)r0 * ldc + c0;
            float* p1 = C + (size_t)(r0 + 8) * ldc + c0;
            float2 v0 = make_float2(acc[mi][ni][0], acc[mi][ni][1]);
            float2 v1 = make_float2(acc[mi][ni][2], acc[mi][ni][3]);
            if (ROUND_OUT) {
                v0.x = rna_tf32(v0.x); v0.y = rna_tf32(v0.y);
                v1.x = rna_tf32(v1.x); v1.y = rna_tf32(v1.y);
            }
            *reinterpret_cast<float2*>(p0) = v0;
            *reinterpret_cast<float2*>(p1) = v1;
        }
    }
}

// ---------------------------------------------------------------------------
// PERSISTENT big GEMM: 296 CTAs, 2 CTAs/SM, 512 THREADS (16 warps, 4x4 grid,
// warp tile 32x32) -> 32 warps/SM = 8/SMSP for latency cover. acc = 32 regs,
// __launch_bounds__(512,2) caps at 64 regs. Fragment rowsum (bn==0 only).
// Same 3-stage ring + balanced unit assignment as before.
// ---------------------------------------------------------------------------
__global__ __launch_bounds__(512, 2)
void tgemm_persist(const float* __restrict__ A, const float* __restrict__ B,
                   float* __restrict__ part, float* __restrict__ rowp)
{
    extern __shared__ float sm[];

    const int cta  = blockIdx.x;                      // 0..295
    int u          = (cta < 272) ? 7 * cta : BIGQ + 6 * (cta - 272);
    const int uend = u + ((cta < 272) ? 7 : 6);

    const int tid  = threadIdx.x;
    const int lane = tid & 31;
    const int wid  = tid >> 5;
    const int wm   = wid & 3;      // 4 warp rows (32 each)
    const int wn   = wid >> 2;     // 4 warp cols (32 each)

    const uint32_t smem_base = (uint32_t)__cvta_generic_to_shared(sm);

    uint32_t a_off, b_off;
    {
        const int ar = wm * 32 + (lane & 7) + ((lane >> 3) & 1) * 8;
        const int ak = ((lane >> 4) & 1) * 4;
        a_off = (uint32_t)(ar * 36 + ak) * 4u;
        const int br = wn * 32 + ((lane >> 4) & 1) * 8 + (lane & 7);
        const int bk = ((lane >> 3) & 1) * 4;
        b_off = (uint32_t)(br * 36 + bk) * 4u + A_FLTS * 4u;
    }
    const int l_r  = tid >> 2;          // 0..127 (512 threads)
    const int l_kv = (tid & 3) * 8;     // 0,8,16,24

    while (u < uend) {
        const int tile   = u >> 4;
        const int kc0    = u & 15;
        const int runlen = min(uend - u, 16 - kc0);
        const int slot   = cta - unit_owner(tile << 4);   // 0..3
        const int bm     = (tile & 63) * 128;
        const int bn     = (tile >> 6) * 128;
        const int kbeg   = kc0 * 512;
        const int T      = runlen * 16;                   // stages of K=32
        const bool do_rs = (bn == 0);

        float acc[2][4][4];
        #pragma unroll
        for (int i = 0; i < 2; i++)
            #pragma unroll
            for (int j = 0; j < 4; j++)
                #pragma unroll
                for (int r = 0; r < 4; r++) acc[i][j][r] = 0.0f;
        float rs[2][2];
        rs[0][0] = rs[0][1] = rs[1][0] = rs[1][1] = 0.0f;

        auto fill = [&](int t) {
            const int k0 = kbeg + t * 32;
            const int s  = t % NSTAGE;
            const uint32_t sA = smem_base + (uint32_t)(s * STAGE_FLTS_N) * 4u;
            const uint32_t sB = sA + A_FLTS * 4u;
            #pragma unroll
            for (int p = 0; p < 2; p++) {
                cp_async16(sA + (uint32_t)(l_r * 36 + l_kv + 4 * p) * 4u,
                           A + (size_t)(bm + l_r) * N_NODES + k0 + l_kv + 4 * p);
            }
            #pragma unroll
            for (int p = 0; p < 2; p++) {
                cp_async16(sB + (uint32_t)(l_r * 36 + l_kv + 4 * p) * 4u,
                           B + (size_t)(bn + l_r) * N_NODES + k0 + l_kv + 4 * p);
            }
        };

        fill(0); cp_commit();
        fill(1); cp_commit();

        for (int t = 0; t < T; t++) {
            cp_wait<1>();
            __syncthreads();
            if (t + 2 < T) fill(t + 2);
            cp_commit();

            const int s = t % NSTAGE;
            const uint32_t stage_b = smem_base + (uint32_t)(s * STAGE_FLTS_N) * 4u;
            const uint32_t a_base = stage_b + a_off;
            const uint32_t b_base = stage_b + b_off;

            #pragma unroll
            for (int k8 = 0; k8 < 32; k8 += 8) {
                const uint32_t kb = (uint32_t)k8 * 4u;
                uint32_t af[2][4];
                #pragma unroll
                for (int mi = 0; mi < 2; mi++)
                    ldsm_x4(af[mi][0], af[mi][1], af[mi][2], af[mi][3],
                            a_base + kb + (uint32_t)(mi * 16 * 36) * 4u);
                uint32_t bf[4][2];
                #pragma unroll
                for (int pi = 0; pi < 2; pi++)
                    ldsm_x4(bf[2 * pi][0], bf[2 * pi][1],
                            bf[2 * pi + 1][0], bf[2 * pi + 1][1],
                            b_base + kb + (uint32_t)(pi * 16 * 36) * 4u);
                #pragma unroll
                for (int mi = 0; mi < 2; mi++)
                    #pragma unroll
                    for (int ni = 0; ni < 4; ni++)
                        mma_tf32(acc[mi][ni], af[mi], bf[ni]);
                if (do_rs) {
                    #pragma unroll
                    for (int mi = 0; mi < 2; mi++) {
                        rs[mi][0] += __uint_as_float(af[mi][0]) + __uint_as_float(af[mi][2]);
                        rs[mi][1] += __uint_as_float(af[mi][1]) + __uint_as_float(af[mi][3]);
                    }
                }
            }
        }

        __syncthreads();    // all warps done reading the ring before next run

        if (do_rs) {
            #pragma unroll
            for (int mi = 0; mi < 2; mi++) {
                #pragma unroll
                for (int j = 0; j < 2; j++) {
                    rs[mi][j] += __shfl_xor_sync(0xffffffffu, rs[mi][j], 1);
                    rs[mi][j] += __shfl_xor_sync(0xffffffffu, rs[mi][j], 2);
                }
            }
            if (wn == 0 && (lane & 3) == 0) {
                const int r = lane >> 2;   // 0..7
                #pragma unroll
                for (int mi = 0; mi < 2; mi++) {
                    rowp[slot * N_NODES + bm + wm * 32 + mi * 16 + r]     = rs[mi][0];
                    rowp[slot * N_NODES + bm + wm * 32 + mi * 16 + 8 + r] = rs[mi][1];
                }
            }
        }

        float* C = part + (size_t)slot * MN;
        #pragma unroll
        for (int mi = 0; mi < 2; mi++) {
            const int r0 = bm + wm * 32 + mi * 16 + (lane >> 2);
            #pragma unroll
            for (int ni = 0; ni < 4; ni++) {
                const int c0 = bn + wn * 32 + ni * 8 + 2 * (lane & 3);
                *reinterpret_cast<float2*>(C + (size_t)r0 * F_DIM + c0) =
                    make_float2(acc[mi][ni][0], acc[mi][ni][1]);
                *reinterpret_cast<float2*>(C + (size_t)(r0 + 8) * F_DIM + c0) =
                    make_float2(acc[mi][ni][2], acc[mi][ni][3]);
            }
        }

        u += runlen;
    }
}

// ---------------------------------------------------------------------------
extern "C" void kernel_launch(void* const* d_in, const int* in_sizes, int n_in,
                              void* d_out, int out_size)
{
    const float* features = (const float*)d_in[0];  // [8192, 256]
    const float* adj      = (const float*)d_in[1];  // [8192, 8192]
    const float* neigh_W  = (const float*)d_in[2];  // [256, 256]
    const float* lin_W    = (const float*)d_in[3];  // [256, 512]
    float* out = (float*)d_out;                     // [8192, 256]

    float *hT, *agg, *feat, *part, *rowp;
    cudaGetSymbolAddress((void**)&hT,   g_hT);
    cudaGetSymbolAddress((void**)&agg,  g_agg);
    cudaGetSymbolAddress((void**)&feat, g_feat);
    cudaGetSymbolAddress((void**)&part, g_part);
    cudaGetSymbolAddress((void**)&rowp, g_rowp);

    cudaFuncSetAttribute(tgemm<false, true >,
                         cudaFuncAttributeMaxDynamicSharedMemorySize, SMEM_N);
    cudaFuncSetAttribute(tgemm<true,  false>,
                         cudaFuncAttributeMaxDynamicSharedMemorySize, SMEM_N);
    cudaFuncSetAttribute(tgemm_persist,
                         cudaFuncAttributeMaxDynamicSharedMemorySize, SMEM_N);

    // 1) feat = round_tf32(features)
    round_copy_kernel<<<1024, 512>>>(features, feat);

    // 2) hT = rna(neigh_W @ feat^T)   M=256, N=8192, K=256
    tgemm<false, true><<<dim3(64, 2), 256, SMEM_N>>>(
        neigh_W, nullptr, feat, hT, F_DIM, F_DIM, F_DIM, N_NODES);

    // 3) zero slot 3 (only conditionally-written slot)
    zero_slot3_kernel<<<2048, 256>>>(part, rowp);

    // 4) persistent balanced adj @ hT^T partials (+ fragment rowsums), 296 CTAs
    //    512 threads: 32 warps/SM for latency hiding
    tgemm_persist<<<NCTA_P, 512, SMEM_N>>>(adj, hT, part, rowp);

    // 5) agg = rna( (sum of 4 slots) / (sum rowsums + 1) )
    reduce_big_kernel<<<2048, 256>>>(part, rowp, agg);

    // 6) out = [feat | agg] @ lin_W^T   (single-pass concat, K=512)
    tgemm<true, false><<<dim3(2, 64), 256, SMEM_N>>>(
        feat, agg, lin_W, out, 2 * F_DIM, F_DIM, 2 * F_DIM, F_DIM);
}

// round 15
// speedup vs baseline: 1.0602x; 1.0602x over previous
#include <cuda_runtime.h>
#include <cstdint>

#define N_NODES 8192
#define F_DIM   256
#define MN      ((size_t)N_NODES * F_DIM)

// Persistent-G2 work assignment: 2048 units = 128 tiles x 16 k-chunks(512).
// 296 CTAs: first 272 own 7 units, last 24 own 6. (272*7 + 24*6 = 2048)
#define NCTA_P   296
#define BIGQ     1904     // 272*7

// Scratch (no cudaMalloc allowed)
__device__ float g_hT[(size_t)F_DIM * N_NODES];   // rna(neigh_W @ feat^T) [256][8192]
__device__ float g_feat[MN];                       // tf32-rounded features
__device__ float g_part[4 * MN];                   // per-slot partials (32MB)
__device__ float g_rowp[4 * N_NODES];              // per-slot partial rowsums

// ---------------------------------------------------------------------------
// helpers
// ---------------------------------------------------------------------------
__device__ __forceinline__ void cp_async16(uint32_t s, const void* g) {
    asm volatile("cp.async.cg.shared.global [%0], [%1], 16;\n" :: "r"(s), "l"(g));
}
__device__ __forceinline__ void cp_commit() { asm volatile("cp.async.commit_group;\n"); }
template <int N> __device__ __forceinline__ void cp_wait() {
    asm volatile("cp.async.wait_group %0;\n" :: "n"(N));
}
__device__ __forceinline__ float rna_tf32(float f) {
    uint32_t r;
    asm("cvt.rna.tf32.f32 %0, %1;\n" : "=r"(r) : "f"(f));
    return __uint_as_float(r);
}
__device__ __forceinline__ void mma_tf32(float* c, const uint32_t* a, const uint32_t* b) {
    asm volatile(
        "mma.sync.aligned.m16n8k8.row.col.f32.tf32.tf32.f32 "
        "{%0,%1,%2,%3}, {%4,%5,%6,%7}, {%8,%9}, {%0,%1,%2,%3};\n"
        : "+f"(c[0]), "+f"(c[1]), "+f"(c[2]), "+f"(c[3])
        : "r"(a[0]), "r"(a[1]), "r"(a[2]), "r"(a[3]), "r"(b[0]), "r"(b[1]));
}
__device__ __forceinline__ void ldsm_x4(uint32_t& r0, uint32_t& r1, uint32_t& r2,
                                        uint32_t& r3, uint32_t a) {
    asm volatile("ldmatrix.sync.aligned.m8n8.x4.shared.b16 {%0,%1,%2,%3}, [%4];\n"
                 : "=r"(r0), "=r"(r1), "=r"(r2), "=r"(r3) : "r"(a));
}
__device__ __forceinline__ int unit_owner(int u) {
    return (u < BIGQ) ? (u / 7) : (272 + (u - BIGQ) / 6);
}

// ---------------------------------------------------------------------------
__global__ void round_copy_kernel(const float* __restrict__ src, float* __restrict__ dst) {
    const size_t i = (size_t)(blockIdx.x * blockDim.x + threadIdx.x) * 4;
    float4 v = *reinterpret_cast<const float4*>(src + i);
    v.x = rna_tf32(v.x); v.y = rna_tf32(v.y);
    v.z = rna_tf32(v.z); v.w = rna_tf32(v.w);
    *reinterpret_cast<float4*>(dst + i) = v;
}

// zero slot 3 of part + rowp (slots 0-2 always written by the persistent GEMM)
__global__ void zero_slot3_kernel(float* __restrict__ part, float* __restrict__ rowp) {
    const size_t g = (size_t)blockIdx.x * blockDim.x + threadIdx.x;
    *reinterpret_cast<float4*>(part + 3 * MN + g * 4) = make_float4(0, 0, 0, 0);
    if (g < N_NODES / 4)
        *reinterpret_cast<float4*>(rowp + 3 * N_NODES + g * 4) = make_float4(0, 0, 0, 0);
}

// ---------------------------------------------------------------------------
// NARROW kernel: tile 128x128x32, 256 threads, 2 CTAs/SM.
//   FUSE_RED=false: plain NT GEMM from A (GEMM1).
//   FUSE_RED=true : A k in [0,256) from A (feat); k in [256,512) computed ON
//     THE FLY as rna((part0+part1+part2+part3)*inv) — the reduce_big fusion.
//   ROUND_OUT: round stored C to tf32.
// ---------------------------------------------------------------------------
#define A_FLTS 4608              // 128*36
#define STAGE_FLTS_N (2 * A_FLTS)
#define NSTAGE 3
#define SMEM_N (NSTAGE * STAGE_FLTS_N * 4)   // 110592

template <bool FUSE_RED, bool ROUND_OUT>
__global__ __launch_bounds__(256, 2)
void tgemm(const float* __restrict__ A,
           const float* __restrict__ part, const float* __restrict__ rowp,
           const float* __restrict__ B, float* __restrict__ C,
           int K, int lda, int ldb, int ldc)
{
    extern __shared__ float sm[];
    __shared__ float s_inv[128];

    const int tid  = threadIdx.x;
    const int lane = tid & 31;
    const int wid  = tid >> 5;
    const int wm   = wid & 1;
    const int wn   = wid >> 1;
    const int bm   = blockIdx.y * 128;
    const int bn   = blockIdx.x * 128;

    const uint32_t smem_base = (uint32_t)__cvta_generic_to_shared(sm);

    if (FUSE_RED) {
        if (tid < 128) {
            const int row = bm + tid;
            s_inv[tid] = 1.0f / (rowp[row] + rowp[N_NODES + row] +
                                 rowp[2 * N_NODES + row] + rowp[3 * N_NODES + row] + 1.0f);
        }
        __syncthreads();
    }

    float acc[4][4][4];
    #pragma unroll
    for (int i = 0; i < 4; i++)
        #pragma unroll
        for (int j = 0; j < 4; j++)
            #pragma unroll
            for (int r = 0; r < 4; r++) acc[i][j][r] = 0.0f;

    uint32_t a_off, b_off;
    {
        const int ar = wm * 64 + (lane & 7) + ((lane >> 3) & 1) * 8;
        const int ak = ((lane >> 4) & 1) * 4;
        a_off = (uint32_t)(ar * 36 + ak) * 4u;
        const int br = wn * 32 + ((lane >> 4) & 1) * 8 + (lane & 7);
        const int bk = ((lane >> 3) & 1) * 4;
        b_off = (uint32_t)(br * 36 + bk) * 4u + A_FLTS * 4u;
    }

    const int a_r  = tid >> 3;
    const int a_kv = (tid & 7) * 4;

    auto fill = [&](int t) {
        const int k0 = t * 32;
        const int s  = t % NSTAGE;
        const uint32_t sA = smem_base + (uint32_t)(s * STAGE_FLTS_N) * 4u;
        const uint32_t sB = sA + A_FLTS * 4u;
        if (FUSE_RED && k0 >= F_DIM) {
            // fused reduce: A tile = rna((sum of 4 part slots) * inv)
            #pragma unroll
            for (int p = 0; p < 4; p++) {
                const int r = a_r + 32 * p;
                const size_t gi = (size_t)(bm + r) * F_DIM + (k0 - F_DIM) + a_kv;
                const float4 v0 = *reinterpret_cast<const float4*>(part + gi);
                const float4 v1 = *reinterpret_cast<const float4*>(part + MN + gi);
                const float4 v2 = *reinterpret_cast<const float4*>(part + 2 * MN + gi);
                const float4 v3 = *reinterpret_cast<const float4*>(part + 3 * MN + gi);
                const float inv = s_inv[r];
                float4 o;
                o.x = rna_tf32((v0.x + v1.x + v2.x + v3.x) * inv);
                o.y = rna_tf32((v0.y + v1.y + v2.y + v3.y) * inv);
                o.z = rna_tf32((v0.z + v1.z + v2.z + v3.z) * inv);
                o.w = rna_tf32((v0.w + v1.w + v2.w + v3.w) * inv);
                *reinterpret_cast<float4*>(sm + s * STAGE_FLTS_N + r * 36 + a_kv) = o;
            }
        } else {
            #pragma unroll
            for (int p = 0; p < 4; p++) {
                const int r = a_r + 32 * p;
                cp_async16(sA + (uint32_t)(r * 36 + a_kv) * 4u,
                           A + (size_t)(bm + r) * lda + k0 + a_kv);
            }
        }
        #pragma unroll
        for (int p = 0; p < 4; p++) {
            const int n = a_r + 32 * p;
            cp_async16(sB + (uint32_t)(n * 36 + a_kv) * 4u,
                       B + (size_t)(bn + n) * ldb + k0 + a_kv);
        }
    };

    const int T = K >> 5;
    fill(0); cp_commit();
    fill(1); cp_commit();

    for (int t = 0; t < T; t++) {
        cp_wait<1>();
        __syncthreads();
        if (t + 2 < T) fill(t + 2);
        cp_commit();

        const int s = t % NSTAGE;
        const uint32_t stage_b = smem_base + (uint32_t)(s * STAGE_FLTS_N) * 4u;
        const uint32_t a_base = stage_b + a_off;
        const uint32_t b_base = stage_b + b_off;

        #pragma unroll
        for (int k8 = 0; k8 < 32; k8 += 8) {
            const uint32_t kb = (uint32_t)k8 * 4u;
            uint32_t af[4][4];
            #pragma unroll
            for (int mi = 0; mi < 4; mi++)
                ldsm_x4(af[mi][0], af[mi][1], af[mi][2], af[mi][3],
                        a_base + kb + (uint32_t)(mi * 16 * 36) * 4u);
            uint32_t bf[4][2];
            #pragma unroll
            for (int pi = 0; pi < 2; pi++)
                ldsm_x4(bf[2 * pi][0], bf[2 * pi][1], bf[2 * pi + 1][0], bf[2 * pi + 1][1],
                        b_base + kb + (uint32_t)(pi * 16 * 36) * 4u);
            #pragma unroll
            for (int mi = 0; mi < 4; mi++)
                #pragma unroll
                for (int ni = 0; ni < 4; ni++)
                    mma_tf32(acc[mi][ni], af[mi], bf[ni]);
        }
    }

    #pragma unroll
    for (int mi = 0; mi < 4; mi++) {
        const int r0 = bm + wm * 64 + mi * 16 + (lane >> 2);
        #pragma unroll
        for (int ni = 0; ni < 4; ni++) {
            const int c0 = bn + wn * 32 + ni * 8 + 2 * (lane & 3);
            float* p0 = C + (size_t)r0 * ldc + c0;
            float* p1 = C + (size_t)(r0 + 8) * ldc + c0;
            float2 v0 = make_float2(acc[mi][ni][0], acc[mi][ni][1]);
            float2 v1 = make_float2(acc[mi][ni][2], acc[mi][ni][3]);
            if (ROUND_OUT) {
                v0.x = rna_tf32(v0.x); v0.y = rna_tf32(v0.y);
                v1.x = rna_tf32(v1.x); v1.y = rna_tf32(v1.y);
            }
            *reinterpret_cast<float2*>(p0) = v0;
            *reinterpret_cast<float2*>(p1) = v1;
        }
    }
}

// ---------------------------------------------------------------------------
// PERSISTENT big GEMM: 296 CTAs, 2 CTAs/SM, tile 128x128, 8 warps (2x4,
// warp tile 64x32) — the R10 measured-best chassis, verbatim.
// ---------------------------------------------------------------------------
__global__ __launch_bounds__(256, 2)
void tgemm_persist(const float* __restrict__ A, const float* __restrict__ B,
                   float* __restrict__ part, float* __restrict__ rowp)
{
    extern __shared__ float sm[];
    __shared__ float s_red[256];

    const int cta  = blockIdx.x;                      // 0..295
    int u          = (cta < 272) ? 7 * cta : BIGQ + 6 * (cta - 272);
    const int uend = u + ((cta < 272) ? 7 : 6);

    const int tid  = threadIdx.x;
    const int lane = tid & 31;
    const int wid  = tid >> 5;
    const int wm   = wid & 1;
    const int wn   = wid >> 1;

    const uint32_t smem_base = (uint32_t)__cvta_generic_to_shared(sm);

    uint32_t a_off, b_off;
    {
        const int ar = wm * 64 + (lane & 7) + ((lane >> 3) & 1) * 8;
        const int ak = ((lane >> 4) & 1) * 4;
        a_off = (uint32_t)(ar * 36 + ak) * 4u;
        const int br = wn * 32 + ((lane >> 4) & 1) * 8 + (lane & 7);
        const int bk = ((lane >> 3) & 1) * 4;
        b_off = (uint32_t)(br * 36 + bk) * 4u + A_FLTS * 4u;
    }
    const int a_r  = tid >> 3;
    const int a_kv = (tid & 7) * 4;

    while (u < uend) {
        const int tile   = u >> 4;
        const int kc0    = u & 15;
        const int runlen = min(uend - u, 16 - kc0);
        const int slot   = cta - unit_owner(tile << 4);   // 0..3
        const int bm     = (tile & 63) * 128;
        const int bn     = (tile >> 6) * 128;
        const int kbeg   = kc0 * 512;
        const int T      = runlen * 16;                   // stages of K=32

        float acc[4][4][4];
        #pragma unroll
        for (int i = 0; i < 4; i++)
            #pragma unroll
            for (int j = 0; j < 4; j++)
                #pragma unroll
                for (int r = 0; r < 4; r++) acc[i][j][r] = 0.0f;
        float row_acc = 0.0f;

        auto fill = [&](int t) {
            const int k0 = kbeg + t * 32;
            const int s  = t % NSTAGE;
            const uint32_t sA = smem_base + (uint32_t)(s * STAGE_FLTS_N) * 4u;
            const uint32_t sB = sA + A_FLTS * 4u;
            #pragma unroll
            for (int p = 0; p < 4; p++) {
                const int r = a_r + 32 * p;
                cp_async16(sA + (uint32_t)(r * 36 + a_kv) * 4u,
                           A + (size_t)(bm + r) * N_NODES + k0 + a_kv);
            }
            #pragma unroll
            for (int p = 0; p < 4; p++) {
                const int n = a_r + 32 * p;
                cp_async16(sB + (uint32_t)(n * 36 + a_kv) * 4u,
                           B + (size_t)(bn + n) * N_NODES + k0 + a_kv);
            }
        };

        fill(0); cp_commit();
        fill(1); cp_commit();

        for (int t = 0; t < T; t++) {
            cp_wait<1>();
            __syncthreads();
            if (t + 2 < T) fill(t + 2);
            cp_commit();

            const int s = t % NSTAGE;
            const uint32_t stage_b = smem_base + (uint32_t)(s * STAGE_FLTS_N) * 4u;
            const uint32_t a_base = stage_b + a_off;
            const uint32_t b_base = stage_b + b_off;

            #pragma unroll
            for (int k8 = 0; k8 < 32; k8 += 8) {
                const uint32_t kb = (uint32_t)k8 * 4u;
                uint32_t af[4][4];
                #pragma unroll
                for (int mi = 0; mi < 4; mi++)
                    ldsm_x4(af[mi][0], af[mi][1], af[mi][2], af[mi][3],
                            a_base + kb + (uint32_t)(mi * 16 * 36) * 4u);
                uint32_t bf[4][2];
                #pragma unroll
                for (int pi = 0; pi < 2; pi++)
                    ldsm_x4(bf[2 * pi][0], bf[2 * pi][1],
                            bf[2 * pi + 1][0], bf[2 * pi + 1][1],
                            b_base + kb + (uint32_t)(pi * 16 * 36) * 4u);
                #pragma unroll
                for (int mi = 0; mi < 4; mi++)
                    #pragma unroll
                    for (int ni = 0; ni < 4; ni++)
                        mma_tf32(acc[mi][ni], af[mi], bf[ni]);
            }

            // fused partial rowsum over adj tile (2 threads per row, 16 vals)
            {
                const float* Ar = sm + s * STAGE_FLTS_N + (tid >> 1) * 36 + (tid & 1) * 16;
                const int rot = (tid >> 1) & 3;
                float st = 0.0f;
                #pragma unroll
                for (int i = 0; i < 4; i++) {
                    const float4 v = *(const float4*)(Ar + (((i + rot) & 3) * 4));
                    st += (v.x + v.y) + (v.z + v.w);
                }
                row_acc += st;
            }
        }

        __syncthreads();    // all warps done reading the ring before next run

        if (bn == 0) {
            s_red[tid] = row_acc;
            __syncthreads();
            if (tid < 128)
                rowp[slot * N_NODES + bm + tid] =
                    s_red[2 * tid] + s_red[2 * tid + 1];
            __syncthreads();
        }

        float* C = part + (size_t)slot * MN;
        #pragma unroll
        for (int mi = 0; mi < 4; mi++) {
            const int r0 = bm + wm * 64 + mi * 16 + (lane >> 2);
            #pragma unroll
            for (int ni = 0; ni < 4; ni++) {
                const int c0 = bn + wn * 32 + ni * 8 + 2 * (lane & 3);
                *reinterpret_cast<float2*>(C + (size_t)r0 * F_DIM + c0) =
                    make_float2(acc[mi][ni][0], acc[mi][ni][1]);
                *reinterpret_cast<float2*>(C + (size_t)(r0 + 8) * F_DIM + c0) =
                    make_float2(acc[mi][ni][2], acc[mi][ni][3]);
            }
        }

        u += runlen;
    }
}

// ---------------------------------------------------------------------------
extern "C" void kernel_launch(void* const* d_in, const int* in_sizes, int n_in,
                              void* d_out, int out_size)
{
    const float* features = (const float*)d_in[0];  // [8192, 256]
    const float* adj      = (const float*)d_in[1];  // [8192, 8192]
    const float* neigh_W  = (const float*)d_in[2];  // [256, 256]
    const float* lin_W    = (const float*)d_in[3];  // [256, 512]
    float* out = (float*)d_out;                     // [8192, 256]

    float *hT, *feat, *part, *rowp;
    cudaGetSymbolAddress((void**)&hT,   g_hT);
    cudaGetSymbolAddress((void**)&feat, g_feat);
    cudaGetSymbolAddress((void**)&part, g_part);
    cudaGetSymbolAddress((void**)&rowp, g_rowp);

    cudaFuncSetAttribute(tgemm<false, true >,
                         cudaFuncAttributeMaxDynamicSharedMemorySize, SMEM_N);
    cudaFuncSetAttribute(tgemm<true,  false>,
                         cudaFuncAttributeMaxDynamicSharedMemorySize, SMEM_N);
    cudaFuncSetAttribute(tgemm_persist,
                         cudaFuncAttributeMaxDynamicSharedMemorySize, SMEM_N);

    // 1) feat = round_tf32(features)
    round_copy_kernel<<<1024, 512>>>(features, feat);

    // 2) hT = rna(neigh_W @ feat^T)   M=256, N=8192, K=256
    tgemm<false, true><<<dim3(64, 2), 256, SMEM_N>>>(
        neigh_W, nullptr, nullptr, feat, hT, F_DIM, F_DIM, F_DIM, N_NODES);

    // 3) zero slot 3 (only conditionally-written slot)
    zero_slot3_kernel<<<2048, 256>>>(part, rowp);

    // 4) persistent balanced adj @ hT^T partials (+ rowsums), 296 CTAs
    tgemm_persist<<<NCTA_P, 256, SMEM_N>>>(adj, hT, part, rowp);

    // 5) out = [feat | rna(reduce(part)/deg)] @ lin_W^T  (K=512, reduce fused
    //    into the A-loader for k>=256 — reduce_big kernel deleted)
    tgemm<true, false><<<dim3(2, 64), 256, SMEM_N>>>(
        feat, part, rowp, lin_W, out, 2 * F_DIM, F_DIM, 2 * F_DIM, F_DIM);
}

// round 16
// speedup vs baseline: 1.1029x; 1.0402x over previous
#include <cuda_runtime.h>
#include <cstdint>

#define N_NODES 8192
#define F_DIM   256
#define MN      ((size_t)N_NODES * F_DIM)

// Persistent-G2 work assignment: 2048 units = 128 tiles x 16 k-chunks(512).
// 296 CTAs: first 272 own 7 units, last 24 own 6. (272*7 + 24*6 = 2048)
#define NCTA_P   296
#define BIGQ     1904     // 272*7

// Scratch (no cudaMalloc allowed)
__device__ float g_hT[(size_t)F_DIM * N_NODES];   // rna(neigh_W @ feat^T) [256][8192]
__device__ float g_agg[MN];                        // (adj@h)/deg, tf32-rounded
__device__ float g_feat[MN];                       // tf32-rounded features (written by G1)
__device__ float g_part[4 * MN];                   // per-slot partials (32MB)
__device__ float g_rowp[4 * N_NODES];              // per-slot partial rowsums

// ---------------------------------------------------------------------------
// helpers
// ---------------------------------------------------------------------------
__device__ __forceinline__ void cp_async16(uint32_t s, const void* g) {
    asm volatile("cp.async.cg.shared.global [%0], [%1], 16;\n" :: "r"(s), "l"(g));
}
__device__ __forceinline__ void cp_commit() { asm volatile("cp.async.commit_group;\n"); }
template <int N> __device__ __forceinline__ void cp_wait() {
    asm volatile("cp.async.wait_group %0;\n" :: "n"(N));
}
__device__ __forceinline__ float rna_tf32(float f) {
    uint32_t r;
    asm("cvt.rna.tf32.f32 %0, %1;\n" : "=r"(r) : "f"(f));
    return __uint_as_float(r);
}
__device__ __forceinline__ void mma_tf32(float* c, const uint32_t* a, const uint32_t* b) {
    asm volatile(
        "mma.sync.aligned.m16n8k8.row.col.f32.tf32.tf32.f32 "
        "{%0,%1,%2,%3}, {%4,%5,%6,%7}, {%8,%9}, {%0,%1,%2,%3};\n"
        : "+f"(c[0]), "+f"(c[1]), "+f"(c[2]), "+f"(c[3])
        : "r"(a[0]), "r"(a[1]), "r"(a[2]), "r"(a[3]), "r"(b[0]), "r"(b[1]));
}
__device__ __forceinline__ void ldsm_x4(uint32_t& r0, uint32_t& r1, uint32_t& r2,
                                        uint32_t& r3, uint32_t a) {
    asm volatile("ldmatrix.sync.aligned.m8n8.x4.shared.b16 {%0,%1,%2,%3}, [%4];\n"
                 : "=r"(r0), "=r"(r1), "=r"(r2), "=r"(r3) : "r"(a));
}
__device__ __forceinline__ int unit_owner(int u) {
    return (u < BIGQ) ? (u / 7) : (272 + (u - BIGQ) / 6);
}

// ---------------------------------------------------------------------------
// zero slot 3 of part + rowp (slots 0-2 always written by the persistent GEMM)
__global__ void zero_slot3_kernel(float* __restrict__ part, float* __restrict__ rowp) {
    const size_t g = (size_t)blockIdx.x * blockDim.x + threadIdx.x;
    *reinterpret_cast<float4*>(part + 3 * MN + g * 4) = make_float4(0, 0, 0, 0);
    if (g < N_NODES / 4)
        *reinterpret_cast<float4*>(rowp + 3 * N_NODES + g * 4) = make_float4(0, 0, 0, 0);
}

__global__ void reduce_big_kernel(const float* __restrict__ part,
                                  const float* __restrict__ rowp,
                                  float* __restrict__ agg) {
    const size_t i = (size_t)(blockIdx.x * blockDim.x + threadIdx.x) * 4;
    const int row = (int)(i >> 8);
    const float inv = 1.0f / (rowp[row] + rowp[N_NODES + row] +
                              rowp[2 * N_NODES + row] + rowp[3 * N_NODES + row] + 1.0f);
    float4 a = *reinterpret_cast<const float4*>(part + i);
    float4 b = *reinterpret_cast<const float4*>(part + MN + i);
    float4 c = *reinterpret_cast<const float4*>(part + 2 * MN + i);
    float4 d = *reinterpret_cast<const float4*>(part + 3 * MN + i);
    float4 o;
    o.x = rna_tf32((a.x + b.x + c.x + d.x) * inv);
    o.y = rna_tf32((a.y + b.y + c.y + d.y) * inv);
    o.z = rna_tf32((a.z + b.z + c.z + d.z) * inv);
    o.w = rna_tf32((a.w + b.w + c.w + d.w) * inv);
    *reinterpret_cast<float4*>(agg + i) = o;
}

// ---------------------------------------------------------------------------
// NARROW kernel: tile 128x128x32, 256 threads, 2 CTAs/SM.
//   CONCAT : A k in [0,256) from A, [256,512) from A2 (per-stage switch)
//   ROUND_OUT: round stored C to tf32 (rna)
//   WRITE_B: CTAs with blockIdx.y==0 also re-read each B stage-tile from smem,
//            round to tf32, and write to feat_out (folds round_copy into G1)
// ---------------------------------------------------------------------------
#define A_FLTS 4608              // 128*36
#define STAGE_FLTS_N (2 * A_FLTS)
#define NSTAGE 3
#define SMEM_N (NSTAGE * STAGE_FLTS_N * 4)   // 110592

template <bool CONCAT, bool ROUND_OUT, bool WRITE_B>
__global__ __launch_bounds__(256, 2)
void tgemm(const float* __restrict__ A, const float* __restrict__ A2,
           const float* __restrict__ B, float* __restrict__ C,
           float* __restrict__ feat_out,
           int K, int lda, int ldb, int ldc)
{
    extern __shared__ float sm[];
    const int tid  = threadIdx.x;
    const int lane = tid & 31;
    const int wid  = tid >> 5;
    const int wm   = wid & 1;
    const int wn   = wid >> 1;
    const int bm   = blockIdx.y * 128;
    const int bn   = blockIdx.x * 128;

    const uint32_t smem_base = (uint32_t)__cvta_generic_to_shared(sm);

    float acc[4][4][4];
    #pragma unroll
    for (int i = 0; i < 4; i++)
        #pragma unroll
        for (int j = 0; j < 4; j++)
            #pragma unroll
            for (int r = 0; r < 4; r++) acc[i][j][r] = 0.0f;

    uint32_t a_off, b_off;
    {
        const int ar = wm * 64 + (lane & 7) + ((lane >> 3) & 1) * 8;
        const int ak = ((lane >> 4) & 1) * 4;
        a_off = (uint32_t)(ar * 36 + ak) * 4u;
        const int br = wn * 32 + ((lane >> 4) & 1) * 8 + (lane & 7);
        const int bk = ((lane >> 3) & 1) * 4;
        b_off = (uint32_t)(br * 36 + bk) * 4u + A_FLTS * 4u;
    }

    const int a_r  = tid >> 3;
    const int a_kv = (tid & 7) * 4;

    auto fill = [&](int t) {
        const int k0 = t * 32;
        const int s  = t % NSTAGE;
        const uint32_t sA = smem_base + (uint32_t)(s * STAGE_FLTS_N) * 4u;
        const uint32_t sB = sA + A_FLTS * 4u;
        const float* Asrc = A;
        int ka = k0;
        if (CONCAT && k0 >= F_DIM) { Asrc = A2; ka = k0 - F_DIM; }
        #pragma unroll
        for (int p = 0; p < 4; p++) {
            const int r = a_r + 32 * p;
            cp_async16(sA + (uint32_t)(r * 36 + a_kv) * 4u,
                       Asrc + (size_t)(bm + r) * lda + ka + a_kv);
        }
        #pragma unroll
        for (int p = 0; p < 4; p++) {
            const int n = a_r + 32 * p;
            cp_async16(sB + (uint32_t)(n * 36 + a_kv) * 4u,
                       B + (size_t)(bn + n) * ldb + k0 + a_kv);
        }
    };

    const int T = K >> 5;
    fill(0); cp_commit();
    fill(1); cp_commit();

    for (int t = 0; t < T; t++) {
        cp_wait<1>();
        __syncthreads();
        if (t + 2 < T) fill(t + 2);
        cp_commit();

        const int s = t % NSTAGE;
        const uint32_t stage_b = smem_base + (uint32_t)(s * STAGE_FLTS_N) * 4u;
        const uint32_t a_base = stage_b + a_off;
        const uint32_t b_base = stage_b + b_off;

        #pragma unroll
        for (int k8 = 0; k8 < 32; k8 += 8) {
            const uint32_t kb = (uint32_t)k8 * 4u;
            uint32_t af[4][4];
            #pragma unroll
            for (int mi = 0; mi < 4; mi++)
                ldsm_x4(af[mi][0], af[mi][1], af[mi][2], af[mi][3],
                        a_base + kb + (uint32_t)(mi * 16 * 36) * 4u);
            uint32_t bf[4][2];
            #pragma unroll
            for (int pi = 0; pi < 2; pi++)
                ldsm_x4(bf[2 * pi][0], bf[2 * pi][1], bf[2 * pi + 1][0], bf[2 * pi + 1][1],
                        b_base + kb + (uint32_t)(pi * 16 * 36) * 4u);
            #pragma unroll
            for (int mi = 0; mi < 4; mi++)
                #pragma unroll
                for (int ni = 0; ni < 4; ni++)
                    mma_tf32(acc[mi][ni], af[mi], bf[ni]);
        }

        // fold of round_copy: bm==0 CTAs write rna(B stage tile) to feat_out
        if (WRITE_B && blockIdx.y == 0) {
            const float* Bs = sm + s * STAGE_FLTS_N + A_FLTS;
            const int k0 = t * 32;
            #pragma unroll
            for (int p = 0; p < 4; p++) {
                const int n = a_r + 32 * p;
                const float4 v = *reinterpret_cast<const float4*>(Bs + n * 36 + a_kv);
                float4 o;
                o.x = rna_tf32(v.x); o.y = rna_tf32(v.y);
                o.z = rna_tf32(v.z); o.w = rna_tf32(v.w);
                *reinterpret_cast<float4*>(
                    feat_out + (size_t)(bn + n) * F_DIM + k0 + a_kv) = o;
            }
        }
    }

    #pragma unroll
    for (int mi = 0; mi < 4; mi++) {
        const int r0 = bm + wm * 64 + mi * 16 + (lane >> 2);
        #pragma unroll
        for (int ni = 0; ni < 4; ni++) {
            const int c0 = bn + wn * 32 + ni * 8 + 2 * (lane & 3);
            float* p0 = C + (size_t)r0 * ldc + c0;
            float* p1 = C + (size_t)(r0 + 8) * ldc + c0;
            float2 v0 = make_float2(acc[mi][ni][0], acc[mi][ni][1]);
            float2 v1 = make_float2(acc[mi][ni][2], acc[mi][ni][3]);
            if (ROUND_OUT) {
                v0.x = rna_tf32(v0.x); v0.y = rna_tf32(v0.y);
                v1.x = rna_tf32(v1.x); v1.y = rna_tf32(v1.y);
            }
            *reinterpret_cast<float2*>(p0) = v0;
            *reinterpret_cast<float2*>(p1) = v1;
        }
    }
}

// ---------------------------------------------------------------------------
// PERSISTENT big GEMM: 296 CTAs, 2 CTAs/SM, tile 128x128, 8 warps (2x4,
// warp tile 64x32) — the R10 measured-best chassis, verbatim (smem rowsum).
// ---------------------------------------------------------------------------
__global__ __launch_bounds__(256, 2)
void tgemm_persist(const float* __restrict__ A, const float* __restrict__ B,
                   float* __restrict__ part, float* __restrict__ rowp)
{
    extern __shared__ float sm[];
    __shared__ float s_red[256];

    const int cta  = blockIdx.x;                      // 0..295
    int u          = (cta < 272) ? 7 * cta : BIGQ + 6 * (cta - 272);
    const int uend = u + ((cta < 272) ? 7 : 6);

    const int tid  = threadIdx.x;
    const int lane = tid & 31;
    const int wid  = tid >> 5;
    const int wm   = wid & 1;
    const int wn   = wid >> 1;

    const uint32_t smem_base = (uint32_t)__cvta_generic_to_shared(sm);

    uint32_t a_off, b_off;
    {
        const int ar = wm * 64 + (lane & 7) + ((lane >> 3) & 1) * 8;
        const int ak = ((lane >> 4) & 1) * 4;
        a_off = (uint32_t)(ar * 36 + ak) * 4u;
        const int br = wn * 32 + ((lane >> 4) & 1) * 8 + (lane & 7);
        const int bk = ((lane >> 3) & 1) * 4;
        b_off = (uint32_t)(br * 36 + bk) * 4u + A_FLTS * 4u;
    }
    const int a_r  = tid >> 3;
    const int a_kv = (tid & 7) * 4;

    while (u < uend) {
        const int tile   = u >> 4;
        const int kc0    = u & 15;
        const int runlen = min(uend - u, 16 - kc0);
        const int slot   = cta - unit_owner(tile << 4);   // 0..3
        const int bm     = (tile & 63) * 128;
        const int bn     = (tile >> 6) * 128;
        const int kbeg   = kc0 * 512;
        const int T      = runlen * 16;                   // stages of K=32

        float acc[4][4][4];
        #pragma unroll
        for (int i = 0; i < 4; i++)
            #pragma unroll
            for (int j = 0; j < 4; j++)
                #pragma unroll
                for (int r = 0; r < 4; r++) acc[i][j][r] = 0.0f;
        float row_acc = 0.0f;

        auto fill = [&](int t) {
            const int k0 = kbeg + t * 32;
            const int s  = t % NSTAGE;
            const uint32_t sA = smem_base + (uint32_t)(s * STAGE_FLTS_N) * 4u;
            const uint32_t sB = sA + A_FLTS * 4u;
            #pragma unroll
            for (int p = 0; p < 4; p++) {
                const int r = a_r + 32 * p;
                cp_async16(sA + (uint32_t)(r * 36 + a_kv) * 4u,
                           A + (size_t)(bm + r) * N_NODES + k0 + a_kv);
            }
            #pragma unroll
            for (int p = 0; p < 4; p++) {
                const int n = a_r + 32 * p;
                cp_async16(sB + (uint32_t)(n * 36 + a_kv) * 4u,
                           B + (size_t)(bn + n) * N_NODES + k0 + a_kv);
            }
        };

        fill(0); cp_commit();
        fill(1); cp_commit();

        for (int t = 0; t < T; t++) {
            cp_wait<1>();
            __syncthreads();
            if (t + 2 < T) fill(t + 2);
            cp_commit();

            const int s = t % NSTAGE;
            const uint32_t stage_b = smem_base + (uint32_t)(s * STAGE_FLTS_N) * 4u;
            const uint32_t a_base = stage_b + a_off;
            const uint32_t b_base = stage_b + b_off;

            #pragma unroll
            for (int k8 = 0; k8 < 32; k8 += 8) {
                const uint32_t kb = (uint32_t)k8 * 4u;
                uint32_t af[4][4];
                #pragma unroll
                for (int mi = 0; mi < 4; mi++)
                    ldsm_x4(af[mi][0], af[mi][1], af[mi][2], af[mi][3],
                            a_base + kb + (uint32_t)(mi * 16 * 36) * 4u);
                uint32_t bf[4][2];
                #pragma unroll
                for (int pi = 0; pi < 2; pi++)
                    ldsm_x4(bf[2 * pi][0], bf[2 * pi][1],
                            bf[2 * pi + 1][0], bf[2 * pi + 1][1],
                            b_base + kb + (uint32_t)(pi * 16 * 36) * 4u);
                #pragma unroll
                for (int mi = 0; mi < 4; mi++)
                    #pragma unroll
                    for (int ni = 0; ni < 4; ni++)
                        mma_tf32(acc[mi][ni], af[mi], bf[ni]);
            }

            // fused partial rowsum over adj tile (2 threads per row, 16 vals)
            {
                const float* Ar = sm + s * STAGE_FLTS_N + (tid >> 1) * 36 + (tid & 1) * 16;
                const int rot = (tid >> 1) & 3;
                float st = 0.0f;
                #pragma unroll
                for (int i = 0; i < 4; i++) {
                    const float4 v = *(const float4*)(Ar + (((i + rot) & 3) * 4));
                    st += (v.x + v.y) + (v.z + v.w);
                }
                row_acc += st;
            }
        }

        __syncthreads();    // all warps done reading the ring before next run

        if (bn == 0) {
            s_red[tid] = row_acc;
            __syncthreads();
            if (tid < 128)
                rowp[slot * N_NODES + bm + tid] =
                    s_red[2 * tid] + s_red[2 * tid + 1];
            __syncthreads();
        }

        float* C = part + (size_t)slot * MN;
        #pragma unroll
        for (int mi = 0; mi < 4; mi++) {
            const int r0 = bm + wm * 64 + mi * 16 + (lane >> 2);
            #pragma unroll
            for (int ni = 0; ni < 4; ni++) {
                const int c0 = bn + wn * 32 + ni * 8 + 2 * (lane & 3);
                *reinterpret_cast<float2*>(C + (size_t)r0 * F_DIM + c0) =
                    make_float2(acc[mi][ni][0], acc[mi][ni][1]);
                *reinterpret_cast<float2*>(C + (size_t)(r0 + 8) * F_DIM + c0) =
                    make_float2(acc[mi][ni][2], acc[mi][ni][3]);
            }
        }

        u += runlen;
    }
}

// ---------------------------------------------------------------------------
extern "C" void kernel_launch(void* const* d_in, const int* in_sizes, int n_in,
                              void* d_out, int out_size)
{
    const float* features = (const float*)d_in[0];  // [8192, 256]
    const float* adj      = (const float*)d_in[1];  // [8192, 8192]
    const float* neigh_W  = (const float*)d_in[2];  // [256, 256]
    const float* lin_W    = (const float*)d_in[3];  // [256, 512]
    float* out = (float*)d_out;                     // [8192, 256]

    float *hT, *agg, *feat, *part, *rowp;
    cudaGetSymbolAddress((void**)&hT,   g_hT);
    cudaGetSymbolAddress((void**)&agg,  g_agg);
    cudaGetSymbolAddress((void**)&feat, g_feat);
    cudaGetSymbolAddress((void**)&part, g_part);
    cudaGetSymbolAddress((void**)&rowp, g_rowp);

    cudaFuncSetAttribute(tgemm<false, true,  true >,
                         cudaFuncAttributeMaxDynamicSharedMemorySize, SMEM_N);
    cudaFuncSetAttribute(tgemm<true,  false, false>,
                         cudaFuncAttributeMaxDynamicSharedMemorySize, SMEM_N);
    cudaFuncSetAttribute(tgemm_persist,
                         cudaFuncAttributeMaxDynamicSharedMemorySize, SMEM_N);

    // 1) hT = rna(neigh_W @ features^T)  (B = raw features; bm==0 CTAs also
    //    write rna(features) -> g_feat, replacing the round_copy pass)
    tgemm<false, true, true><<<dim3(64, 2), 256, SMEM_N>>>(
        neigh_W, nullptr, features, hT, feat, F_DIM, F_DIM, F_DIM, N_NODES);

    // 2) zero slot 3 (only conditionally-written slot)
    zero_slot3_kernel<<<2048, 256>>>(part, rowp);

    // 3) persistent balanced adj @ hT^T partials (+ rowsums), 296 CTAs
    tgemm_persist<<<NCTA_P, 256, SMEM_N>>>(adj, hT, part, rowp);

    // 4) agg = rna( (sum of 4 slots) / (sum rowsums + 1) )
    reduce_big_kernel<<<2048, 256>>>(part, rowp, agg);

    // 5) out = [feat | agg] @ lin_W^T   (single-pass concat, K=512)
    tgemm<true, false, false><<<dim3(2, 64), 256, SMEM_N>>>(
        feat, agg, lin_W, out, nullptr, 2 * F_DIM, F_DIM, 2 * F_DIM, F_DIM);
}

// round 17
// speedup vs baseline: 1.1143x; 1.0103x over previous
#include <cuda_runtime.h>
#include <cstdint>

#define N_NODES 8192
#define F_DIM   256
#define MN      ((size_t)N_NODES * F_DIM)

// Persistent-G2 work assignment: 2048 units = 128 tiles x 16 k-chunks(512).
// 296 CTAs: first 272 own 7 units, last 24 own 6. (272*7 + 24*6 = 2048)
#define NCTA_P   296
#define BIGQ     1904     // 272*7

// Scratch (no cudaMalloc allowed)
__device__ float g_hT[(size_t)F_DIM * N_NODES];   // rna(neigh_W @ feat^T) [256][8192]
__device__ float g_agg[MN];                        // (adj@h)/deg, tf32-rounded
__device__ float g_feat[MN];                       // tf32-rounded features (written by G1)
__device__ float g_part[4 * MN];                   // per-slot partials (32MB)
__device__ float g_rowp[4 * N_NODES];              // per-slot partial rowsums

// ---------------------------------------------------------------------------
// helpers
// ---------------------------------------------------------------------------
__device__ __forceinline__ void cp_async16(uint32_t s, const void* g) {
    asm volatile("cp.async.cg.shared.global [%0], [%1], 16;\n" :: "r"(s), "l"(g));
}
__device__ __forceinline__ void cp_commit() { asm volatile("cp.async.commit_group;\n"); }
template <int N> __device__ __forceinline__ void cp_wait() {
    asm volatile("cp.async.wait_group %0;\n" :: "n"(N));
}
__device__ __forceinline__ float rna_tf32(float f) {
    uint32_t r;
    asm("cvt.rna.tf32.f32 %0, %1;\n" : "=r"(r) : "f"(f));
    return __uint_as_float(r);
}
__device__ __forceinline__ void mma_tf32(float* c, const uint32_t* a, const uint32_t* b) {
    asm volatile(
        "mma.sync.aligned.m16n8k8.row.col.f32.tf32.tf32.f32 "
        "{%0,%1,%2,%3}, {%4,%5,%6,%7}, {%8,%9}, {%0,%1,%2,%3};\n"
        : "+f"(c[0]), "+f"(c[1]), "+f"(c[2]), "+f"(c[3])
        : "r"(a[0]), "r"(a[1]), "r"(a[2]), "r"(a[3]), "r"(b[0]), "r"(b[1]));
}
__device__ __forceinline__ void ldsm_x4(uint32_t& r0, uint32_t& r1, uint32_t& r2,
                                        uint32_t& r3, uint32_t a) {
    asm volatile("ldmatrix.sync.aligned.m8n8.x4.shared.b16 {%0,%1,%2,%3}, [%4];\n"
                 : "=r"(r0), "=r"(r1), "=r"(r2), "=r"(r3) : "r"(a));
}
__device__ __forceinline__ int unit_owner(int u) {
    return (u < BIGQ) ? (u / 7) : (272 + (u - BIGQ) / 6);
}
// number of G2 slots actually written for output tile t (0..127)
__device__ __forceinline__ int nslots(int t) {
    return unit_owner((t << 4) + 15) - unit_owner(t << 4) + 1;
}

// ---------------------------------------------------------------------------
// Slot-aware reduce: agg = rna( (sum of LIVE slots) / (sum live rowsums + 1) ).
// nslots derived in closed form from the G2 assignment — unwritten slots are
// never read, so no zero-fill pass is needed at all.
// ---------------------------------------------------------------------------
__global__ void reduce_big_kernel(const float* __restrict__ part,
                                  const float* __restrict__ rowp,
                                  float* __restrict__ agg) {
    const size_t i = (size_t)(blockIdx.x * blockDim.x + threadIdx.x) * 4;
    const int row = (int)(i >> 8);       // 0..8191
    const int col = (int)(i & 255);      // 0..255
    const int t0  = row >> 7;            // bm tile index (0..63)

    // degree: live rowp slots of the bn==0 tile (tile id = t0)
    const int nsr = nslots(t0);
    float deg = rowp[row];
    for (int s = 1; s < nsr; s++) deg += rowp[(size_t)s * N_NODES + row];
    const float inv = 1.0f / (deg + 1.0f);

    // partials: live slots of this element's tile (bn from column half)
    const int tile = t0 + ((col >= 128) ? 64 : 0);
    const int ns = nslots(tile);
    float4 a = *reinterpret_cast<const float4*>(part + i);
    for (int s = 1; s < ns; s++) {
        const float4 v = *reinterpret_cast<const float4*>(part + (size_t)s * MN + i);
        a.x += v.x; a.y += v.y; a.z += v.z; a.w += v.w;
    }
    float4 o;
    o.x = rna_tf32(a.x * inv);
    o.y = rna_tf32(a.y * inv);
    o.z = rna_tf32(a.z * inv);
    o.w = rna_tf32(a.w * inv);
    *reinterpret_cast<float4*>(agg + i) = o;
}

// ---------------------------------------------------------------------------
// NARROW kernel: tile 128x128x32, 256 threads, 2 CTAs/SM.
//   CONCAT : A k in [0,256) from A, [256,512) from A2 (per-stage switch)
//   ROUND_OUT: round stored C to tf32 (rna)
//   WRITE_B: CTAs with blockIdx.y==0 also re-read each B stage-tile from smem,
//            round to tf32, and write to feat_out (folds round_copy into G1)
// ---------------------------------------------------------------------------
#define A_FLTS 4608              // 128*36
#define STAGE_FLTS_N (2 * A_FLTS)
#define NSTAGE 3
#define SMEM_N (NSTAGE * STAGE_FLTS_N * 4)   // 110592

template <bool CONCAT, bool ROUND_OUT, bool WRITE_B>
__global__ __launch_bounds__(256, 2)
void tgemm(const float* __restrict__ A, const float* __restrict__ A2,
           const float* __restrict__ B, float* __restrict__ C,
           float* __restrict__ feat_out,
           int K, int lda, int ldb, int ldc)
{
    extern __shared__ float sm[];
    const int tid  = threadIdx.x;
    const int lane = tid & 31;
    const int wid  = tid >> 5;
    const int wm   = wid & 1;
    const int wn   = wid >> 1;
    const int bm   = blockIdx.y * 128;
    const int bn   = blockIdx.x * 128;

    const uint32_t smem_base = (uint32_t)__cvta_generic_to_shared(sm);

    float acc[4][4][4];
    #pragma unroll
    for (int i = 0; i < 4; i++)
        #pragma unroll
        for (int j = 0; j < 4; j++)
            #pragma unroll
            for (int r = 0; r < 4; r++) acc[i][j][r] = 0.0f;

    uint32_t a_off, b_off;
    {
        const int ar = wm * 64 + (lane & 7) + ((lane >> 3) & 1) * 8;
        const int ak = ((lane >> 4) & 1) * 4;
        a_off = (uint32_t)(ar * 36 + ak) * 4u;
        const int br = wn * 32 + ((lane >> 4) & 1) * 8 + (lane & 7);
        const int bk = ((lane >> 3) & 1) * 4;
        b_off = (uint32_t)(br * 36 + bk) * 4u + A_FLTS * 4u;
    }

    const int a_r  = tid >> 3;
    const int a_kv = (tid & 7) * 4;

    auto fill = [&](int t) {
        const int k0 = t * 32;
        const int s  = t % NSTAGE;
        const uint32_t sA = smem_base + (uint32_t)(s * STAGE_FLTS_N) * 4u;
        const uint32_t sB = sA + A_FLTS * 4u;
        const float* Asrc = A;
        int ka = k0;
        if (CONCAT && k0 >= F_DIM) { Asrc = A2; ka = k0 - F_DIM; }
        #pragma unroll
        for (int p = 0; p < 4; p++) {
            const int r = a_r + 32 * p;
            cp_async16(sA + (uint32_t)(r * 36 + a_kv) * 4u,
                       Asrc + (size_t)(bm + r) * lda + ka + a_kv);
        }
        #pragma unroll
        for (int p = 0; p < 4; p++) {
            const int n = a_r + 32 * p;
            cp_async16(sB + (uint32_t)(n * 36 + a_kv) * 4u,
                       B + (size_t)(bn + n) * ldb + k0 + a_kv);
        }
    };

    const int T = K >> 5;
    fill(0); cp_commit();
    fill(1); cp_commit();

    for (int t = 0; t < T; t++) {
        cp_wait<1>();
        __syncthreads();
        if (t + 2 < T) fill(t + 2);
        cp_commit();

        const int s = t % NSTAGE;
        const uint32_t stage_b = smem_base + (uint32_t)(s * STAGE_FLTS_N) * 4u;
        const uint32_t a_base = stage_b + a_off;
        const uint32_t b_base = stage_b + b_off;

        #pragma unroll
        for (int k8 = 0; k8 < 32; k8 += 8) {
            const uint32_t kb = (uint32_t)k8 * 4u;
            uint32_t af[4][4];
            #pragma unroll
            for (int mi = 0; mi < 4; mi++)
                ldsm_x4(af[mi][0], af[mi][1], af[mi][2], af[mi][3],
                        a_base + kb + (uint32_t)(mi * 16 * 36) * 4u);
            uint32_t bf[4][2];
            #pragma unroll
            for (int pi = 0; pi < 2; pi++)
                ldsm_x4(bf[2 * pi][0], bf[2 * pi][1], bf[2 * pi + 1][0], bf[2 * pi + 1][1],
                        b_base + kb + (uint32_t)(pi * 16 * 36) * 4u);
            #pragma unroll
            for (int mi = 0; mi < 4; mi++)
                #pragma unroll
                for (int ni = 0; ni < 4; ni++)
                    mma_tf32(acc[mi][ni], af[mi], bf[ni]);
        }

        // fold of round_copy: bm==0 CTAs write rna(B stage tile) to feat_out
        if (WRITE_B && blockIdx.y == 0) {
            const float* Bs = sm + s * STAGE_FLTS_N + A_FLTS;
            const int k0 = t * 32;
            #pragma unroll
            for (int p = 0; p < 4; p++) {
                const int n = a_r + 32 * p;
                const float4 v = *reinterpret_cast<const float4*>(Bs + n * 36 + a_kv);
                float4 o;
                o.x = rna_tf32(v.x); o.y = rna_tf32(v.y);
                o.z = rna_tf32(v.z); o.w = rna_tf32(v.w);
                *reinterpret_cast<float4*>(
                    feat_out + (size_t)(bn + n) * F_DIM + k0 + a_kv) = o;
            }
        }
    }

    #pragma unroll
    for (int mi = 0; mi < 4; mi++) {
        const int r0 = bm + wm * 64 + mi * 16 + (lane >> 2);
        #pragma unroll
        for (int ni = 0; ni < 4; ni++) {
            const int c0 = bn + wn * 32 + ni * 8 + 2 * (lane & 3);
            float* p0 = C + (size_t)r0 * ldc + c0;
            float* p1 = C + (size_t)(r0 + 8) * ldc + c0;
            float2 v0 = make_float2(acc[mi][ni][0], acc[mi][ni][1]);
            float2 v1 = make_float2(acc[mi][ni][2], acc[mi][ni][3]);
            if (ROUND_OUT) {
                v0.x = rna_tf32(v0.x); v0.y = rna_tf32(v0.y);
                v1.x = rna_tf32(v1.x); v1.y = rna_tf32(v1.y);
            }
            *reinterpret_cast<float2*>(p0) = v0;
            *reinterpret_cast<float2*>(p1) = v1;
        }
    }
}

// ---------------------------------------------------------------------------
// PERSISTENT big GEMM: 296 CTAs, 2 CTAs/SM, tile 128x128, 8 warps (2x4,
// warp tile 64x32) — the R10 measured-best chassis, verbatim (smem rowsum).
// ---------------------------------------------------------------------------
__global__ __launch_bounds__(256, 2)
void tgemm_persist(const float* __restrict__ A, const float* __restrict__ B,
                   float* __restrict__ part, float* __restrict__ rowp)
{
    extern __shared__ float sm[];
    __shared__ float s_red[256];

    const int cta  = blockIdx.x;                      // 0..295
    int u          = (cta < 272) ? 7 * cta : BIGQ + 6 * (cta - 272);
    const int uend = u + ((cta < 272) ? 7 : 6);

    const int tid  = threadIdx.x;
    const int lane = tid & 31;
    const int wid  = tid >> 5;
    const int wm   = wid & 1;
    const int wn   = wid >> 1;

    const uint32_t smem_base = (uint32_t)__cvta_generic_to_shared(sm);

    uint32_t a_off, b_off;
    {
        const int ar = wm * 64 + (lane & 7) + ((lane >> 3) & 1) * 8;
        const int ak = ((lane >> 4) & 1) * 4;
        a_off = (uint32_t)(ar * 36 + ak) * 4u;
        const int br = wn * 32 + ((lane >> 4) & 1) * 8 + (lane & 7);
        const int bk = ((lane >> 3) & 1) * 4;
        b_off = (uint32_t)(br * 36 + bk) * 4u + A_FLTS * 4u;
    }
    const int a_r  = tid >> 3;
    const int a_kv = (tid & 7) * 4;

    while (u < uend) {
        const int tile   = u >> 4;
        const int kc0    = u & 15;
        const int runlen = min(uend - u, 16 - kc0);
        const int slot   = cta - unit_owner(tile << 4);   // 0..3
        const int bm     = (tile & 63) * 128;
        const int bn     = (tile >> 6) * 128;
        const int kbeg   = kc0 * 512;
        const int T      = runlen * 16;                   // stages of K=32

        float acc[4][4][4];
        #pragma unroll
        for (int i = 0; i < 4; i++)
            #pragma unroll
            for (int j = 0; j < 4; j++)
                #pragma unroll
                for (int r = 0; r < 4; r++) acc[i][j][r] = 0.0f;
        float row_acc = 0.0f;

        auto fill = [&](int t) {
            const int k0 = kbeg + t * 32;
            const int s  = t % NSTAGE;
            const uint32_t sA = smem_base + (uint32_t)(s * STAGE_FLTS_N) * 4u;
            const uint32_t sB = sA + A_FLTS * 4u;
            #pragma unroll
            for (int p = 0; p < 4; p++) {
                const int r = a_r + 32 * p;
                cp_async16(sA + (uint32_t)(r * 36 + a_kv) * 4u,
                           A + (size_t)(bm + r) * N_NODES + k0 + a_kv);
            }
            #pragma unroll
            for (int p = 0; p < 4; p++) {
                const int n = a_r + 32 * p;
                cp_async16(sB + (uint32_t)(n * 36 + a_kv) * 4u,
                           B + (size_t)(bn + n) * N_NODES + k0 + a_kv);
            }
        };

        fill(0); cp_commit();
        fill(1); cp_commit();

        for (int t = 0; t < T; t++) {
            cp_wait<1>();
            __syncthreads();
            if (t + 2 < T) fill(t + 2);
            cp_commit();

            const int s = t % NSTAGE;
            const uint32_t stage_b = smem_base + (uint32_t)(s * STAGE_FLTS_N) * 4u;
            const uint32_t a_base = stage_b + a_off;
            const uint32_t b_base = stage_b + b_off;

            #pragma unroll
            for (int k8 = 0; k8 < 32; k8 += 8) {
                const uint32_t kb = (uint32_t)k8 * 4u;
                uint32_t af[4][4];
                #pragma unroll
                for (int mi = 0; mi < 4; mi++)
                    ldsm_x4(af[mi][0], af[mi][1], af[mi][2], af[mi][3],
                            a_base + kb + (uint32_t)(mi * 16 * 36) * 4u);
                uint32_t bf[4][2];
                #pragma unroll
                for (int pi = 0; pi < 2; pi++)
                    ldsm_x4(bf[2 * pi][0], bf[2 * pi][1],
                            bf[2 * pi + 1][0], bf[2 * pi + 1][1],
                            b_base + kb + (uint32_t)(pi * 16 * 36) * 4u);
                #pragma unroll
                for (int mi = 0; mi < 4; mi++)
                    #pragma unroll
                    for (int ni = 0; ni < 4; ni++)
                        mma_tf32(acc[mi][ni], af[mi], bf[ni]);
            }

            // fused partial rowsum over adj tile (2 threads per row, 16 vals)
            {
                const float* Ar = sm + s * STAGE_FLTS_N + (tid >> 1) * 36 + (tid & 1) * 16;
                const int rot = (tid >> 1) & 3;
                float st = 0.0f;
                #pragma unroll
                for (int i = 0; i < 4; i++) {
                    const float4 v = *(const float4*)(Ar + (((i + rot) & 3) * 4));
                    st += (v.x + v.y) + (v.z + v.w);
                }
                row_acc += st;
            }
        }

        __syncthreads();    // all warps done reading the ring before next run

        if (bn == 0) {
            s_red[tid] = row_acc;
            __syncthreads();
            if (tid < 128)
                rowp[slot * N_NODES + bm + tid] =
                    s_red[2 * tid] + s_red[2 * tid + 1];
            __syncthreads();
        }

        float* C = part + (size_t)slot * MN;
        #pragma unroll
        for (int mi = 0; mi < 4; mi++) {
            const int r0 = bm + wm * 64 + mi * 16 + (lane >> 2);
            #pragma unroll
            for (int ni = 0; ni < 4; ni++) {
                const int c0 = bn + wn * 32 + ni * 8 + 2 * (lane & 3);
                *reinterpret_cast<float2*>(C + (size_t)r0 * F_DIM + c0) =
                    make_float2(acc[mi][ni][0], acc[mi][ni][1]);
                *reinterpret_cast<float2*>(C + (size_t)(r0 + 8) * F_DIM + c0) =
                    make_float2(acc[mi][ni][2], acc[mi][ni][3]);
            }
        }

        u += runlen;
    }
}

// ---------------------------------------------------------------------------
extern "C" void kernel_launch(void* const* d_in, const int* in_sizes, int n_in,
                              void* d_out, int out_size)
{
    const float* features = (const float*)d_in[0];  // [8192, 256]
    const float* adj      = (const float*)d_in[1];  // [8192, 8192]
    const float* neigh_W  = (const float*)d_in[2];  // [256, 256]
    const float* lin_W    = (const float*)d_in[3];  // [256, 512]
    float* out = (float*)d_out;                     // [8192, 256]

    float *hT, *agg, *feat, *part, *rowp;
    cudaGetSymbolAddress((void**)&hT,   g_hT);
    cudaGetSymbolAddress((void**)&agg,  g_agg);
    cudaGetSymbolAddress((void**)&feat, g_feat);
    cudaGetSymbolAddress((void**)&part, g_part);
    cudaGetSymbolAddress((void**)&rowp, g_rowp);

    cudaFuncSetAttribute(tgemm<false, true,  true >,
                         cudaFuncAttributeMaxDynamicSharedMemorySize, SMEM_N);
    cudaFuncSetAttribute(tgemm<true,  false, false>,
                         cudaFuncAttributeMaxDynamicSharedMemorySize, SMEM_N);
    cudaFuncSetAttribute(tgemm_persist,
                         cudaFuncAttributeMaxDynamicSharedMemorySize, SMEM_N);

    // 1) hT = rna(neigh_W @ features^T)  (B = raw features; bm==0 CTAs also
    //    write rna(features) -> g_feat, replacing the round_copy pass)
    tgemm<false, true, true><<<dim3(64, 2), 256, SMEM_N>>>(
        neigh_W, nullptr, features, hT, feat, F_DIM, F_DIM, F_DIM, N_NODES);

    // 2) persistent balanced adj @ hT^T partials (+ rowsums), 296 CTAs
    tgemm_persist<<<NCTA_P, 256, SMEM_N>>>(adj, hT, part, rowp);

    // 3) agg = rna( (sum of LIVE slots) / (sum live rowsums + 1) )
    //    nslots computed in closed form — no zero-fill pass needed
    reduce_big_kernel<<<2048, 256>>>(part, rowp, agg);

    // 4) out = [feat | agg] @ lin_W^T   (single-pass concat, K=512)
    tgemm<true, false, false><<<dim3(2, 64), 256, SMEM_N>>>(
        feat, agg, lin_W, out, nullptr, 2 * F_DIM, F_DIM, 2 * F_DIM, F_DIM);
}